// round 9
// baseline (speedup 1.0000x reference)
#include <cuda_runtime.h>
#include <math.h>

typedef unsigned long long ull;
#define BATCHN 8192
#define INDIM 512
#define PI_F 3.14159265358979323846f

// ---------- f32x2 packed primitives ----------
__device__ __forceinline__ ull pk(float x, float y) {
    ull r; asm("mov.b64 %0, {%1, %2};" : "=l"(r) : "f"(x), "f"(y)); return r;
}
__device__ __forceinline__ float2 upk(ull v) {
    float2 f; asm("mov.b64 {%0, %1}, %2;" : "=f"(f.x), "=f"(f.y) : "l"(v)); return f;
}
__device__ __forceinline__ ull spl(float x) { return pk(x, x); }
__device__ __forceinline__ ull f2fma(ull a, ull b, ull c) {
    ull d; asm("fma.rn.f32x2 %0, %1, %2, %3;" : "=l"(d) : "l"(a), "l"(b), "l"(c)); return d;
}
__device__ __forceinline__ ull f2mul(ull a, ull b) {
    ull d; asm("mul.rn.f32x2 %0, %1, %2;" : "=l"(d) : "l"(a), "l"(b)); return d;
}
__device__ __forceinline__ ull f2add(ull a, ull b) {
    ull d; asm("add.rn.f32x2 %0, %1, %2;" : "=l"(d) : "l"(a), "l"(b)); return d;
}
__device__ __forceinline__ ull shx64(ull v, int m) {
    float2 f = upk(v);
    f.x = __shfl_xor_sync(0xffffffffu, f.x, m);
    f.y = __shfl_xor_sync(0xffffffffu, f.y, m);
    return pk(f.x, f.y);
}
__device__ __forceinline__ float2 cmul(float2 a, float2 b) {
    return make_float2(a.x * b.x - a.y * b.y, a.x * b.y + a.y * b.x);
}

struct __align__(16) GateSplats { ull u00r, u00i, nu00i, u01r, nu01r, u01i, nu01i, pad; };
struct __align__(16) VSplats   { ull v00r, v00i, nv00i, v01r, v01i, nv01i, p0, p1; };

// ======== layout (T=16) ========
// warp = 2 batch elements; element e = lane>>4, sub-lane s = lane&15.
// amp index i[7:0]: bits[7:4] = s (s3=bit7..s0=bit4), bits[3:1] = pack j
// (j2=bit3, j1=bit2, j0=bit1), bit0 = half h. wire w <-> amp bit 7-w.
// wires 0..3 -> lane bits 3,2,1,0 | wires 4,5,6 -> pack bits 4,2,1 | wire 7 -> half.

template<int CS>
__device__ __forceinline__ void gate_shfl(ull R[8], ull I[8], unsigned lane, const GateSplats* gp) {
    const ulonglong2* q = reinterpret_cast<const ulonglong2*>(gp);
    ulonglong2 q0 = q[0], q1 = q[1], q2 = q[2], q3 = q[3];
    ull u00r = q0.x, u00i = q0.y, nu00i = q1.x, u01r = q1.y;
    ull nu01r = q2.x, u01i = q2.y, nu01i = q3.x;
    bool bit = (lane >> CS) & 1;
    ull CMr  = u00r;
    ull CMi  = bit ? nu00i : u00i;
    ull nCMi = bit ? u00i  : nu00i;
    ull COr  = bit ? nu01r : u01r;
    ull COi  = u01i, nCOi = nu01i;
    #pragma unroll
    for (int j = 0; j < 8; j++) {
        ull oR = shx64(R[j], 1 << CS), oI = shx64(I[j], 1 << CS);
        ull sR = R[j], sI = I[j];
        R[j] = f2fma(CMr, sR, f2fma(nCMi, sI, f2fma(COr, oR, f2mul(nCOi, oI))));
        I[j] = f2fma(CMr, sI, f2fma(CMi, sR, f2fma(COr, oI, f2mul(COi, oR))));
    }
}

template<int PM>
__device__ __forceinline__ void gate_cross(ull R[8], ull I[8], const GateSplats* gp) {
    const ulonglong2* q = reinterpret_cast<const ulonglong2*>(gp);
    ulonglong2 q0 = q[0], q1 = q[1], q2 = q[2], q3 = q[3];
    ull u00r = q0.x, u00i = q0.y, nu00i = q1.x, u01r = q1.y;
    ull nu01r = q2.x, u01i = q2.y, nu01i = q3.x;
    #pragma unroll
    for (int j = 0; j < 8; j++) {
        if (!(j & PM)) {
            ull aR = R[j], aI = I[j], bR = R[j | PM], bI = I[j | PM];
            R[j]      = f2fma(u00r,  aR, f2fma(nu00i, aI, f2fma(u01r, bR, f2mul(nu01i, bI))));
            I[j]      = f2fma(u00r,  aI, f2fma(u00i,  aR, f2fma(u01r, bI, f2mul(u01i,  bR))));
            R[j | PM] = f2fma(nu01r, aR, f2fma(nu01i, aI, f2fma(u00r, bR, f2mul(u00i,  bI))));
            I[j | PM] = f2fma(nu01r, aI, f2fma(u01i,  aR, f2fma(u00r, bI, f2mul(nu00i, bR))));
        }
    }
}

__device__ __forceinline__ void gate_v(ull R[8], ull I[8], const VSplats* vp) {
    const ulonglong2* q = reinterpret_cast<const ulonglong2*>(vp);
    ulonglong2 q0 = q[0], q1 = q[1], q2 = q[2];
    ull v00r = q0.x, v00i = q0.y, nv00i = q1.x, v01r = q1.y, v01i = q2.x, nv01i = q2.y;
    #pragma unroll
    for (int j = 0; j < 8; j++) {
        float2 fr = upk(R[j]), fi = upk(I[j]);
        ull aRe = spl(fr.x), bRe = spl(fr.y), aIm = spl(fi.x), bIm = spl(fi.y);
        R[j] = f2fma(v00r, aRe, f2fma(nv00i, aIm, f2fma(v01r, bRe, f2mul(nv01i, bIm))));
        I[j] = f2fma(v00r, aIm, f2fma(v00i,  aRe, f2fma(v01r, bIm, f2mul(v01i,  bRe))));
    }
}

template<int CS, int LM>
__device__ __forceinline__ void cnot_ll(ull R[8], ull I[8], unsigned lane) {
    bool cb = (lane >> CS) & 1;
    #pragma unroll
    for (int j = 0; j < 8; j++) {
        ull o = shx64(R[j], LM); R[j] = cb ? o : R[j];
        o = shx64(I[j], LM);     I[j] = cb ? o : I[j];
    }
}
template<int CS, int PM>
__device__ __forceinline__ void cnot_lp(ull R[8], ull I[8], unsigned lane) {
    bool cb = (lane >> CS) & 1;
    #pragma unroll
    for (int j = 0; j < 8; j++) {
        if (!(j & PM)) {
            ull a = R[j], b = R[j | PM];
            R[j] = cb ? b : a; R[j | PM] = cb ? a : b;
            a = I[j]; b = I[j | PM];
            I[j] = cb ? b : a; I[j | PM] = cb ? a : b;
        }
    }
}
template<int PM>
__device__ __forceinline__ void cnot_ph(ull R[8], ull I[8]) {
    #pragma unroll
    for (int j = 0; j < 8; j++) {
        if (j & PM) {
            float2 r = upk(R[j]); R[j] = pk(r.y, r.x);
            float2 i = upk(I[j]); I[j] = pk(i.y, i.x);
        }
    }
}
template<int PM, int LM>
__device__ __forceinline__ void cnot_pl(ull R[8], ull I[8]) {
    #pragma unroll
    for (int j = 0; j < 8; j++) {
        if (j & PM) { R[j] = shx64(R[j], LM); I[j] = shx64(I[j], LM); }
    }
}
template<int LM>
__device__ __forceinline__ void cnot_hl(ull R[8], ull I[8]) {
    #pragma unroll
    for (int j = 0; j < 8; j++) {
        float2 r = upk(R[j]);
        r.y = __shfl_xor_sync(0xffffffffu, r.y, LM);
        R[j] = pk(r.x, r.y);
        float2 i = upk(I[j]);
        i.y = __shfl_xor_sync(0xffffffffu, i.y, LM);
        I[j] = pk(i.x, i.y);
    }
}

#define SWAPJ(a, b) { ull t_ = R[a]; R[a] = R[b]; R[b] = t_; t_ = I[a]; I[a] = I[b]; I[b] = t_; }

__global__ __launch_bounds__(128, 6) void qlayer_kernel(
    const float* __restrict__ x,
    const float* __restrict__ W,
    const float* __restrict__ bvec,
    const float* __restrict__ scale,
    const float* __restrict__ bias,
    const float* __restrict__ qw,
    float* __restrict__ out)
{
    __shared__ float sW[8][512];          // 16 KB
    __shared__ GateSplats sSp[2][8];
    __shared__ VSplats sV[2];
    __shared__ float2 sG0[8][4];
    __shared__ uint4 sPv[16];             // 256 perm bytes
    __shared__ float sPar[24];            // bvec | scale | bias

    const int tid = threadIdx.x;

    for (int i = tid; i < 1024; i += 128)
        ((float4*)sW)[i] = ((const float4*)W)[i];

    if (tid < 24) {
        sPar[tid] = (tid < 8) ? bvec[tid] : (tid < 16) ? scale[tid - 8] : bias[tid - 16];
        int l = tid >> 3, w = tid & 7;
        const float* qp = qw + (l * 8 + w) * 3;
        float phi = qp[0], th = qp[1], om = qp[2];
        float ct, st_; sincosf(0.5f * th, &st_, &ct);
        float c0, s0, c1, s1;
        sincosf(0.5f * (phi + om), &s0, &c0);
        sincosf(0.5f * (phi - om), &s1, &c1);
        float2 u00 = make_float2(ct * c0, -ct * s0);
        float2 u01 = make_float2(-st_ * c1, -st_ * s1);
        if (l == 0) {
            sG0[w][0] = u00;
            sG0[w][1] = u01;
            sG0[w][2] = make_float2(st_ * c1, -st_ * s1);  // u10
            sG0[w][3] = make_float2(ct * c0, ct * s0);     // u11
        } else {
            GateSplats& g = sSp[l - 1][w];
            g.u00r = spl(u00.x); g.u00i = spl(u00.y); g.nu00i = spl(-u00.y);
            g.u01r = spl(u01.x); g.nu01r = spl(-u01.x);
            g.u01i = spl(u01.y); g.nu01i = spl(-u01.y);
            g.pad = 0;
            if (w == 7) {
                float2 u10 = make_float2(-u01.x, u01.y);
                float2 u11 = make_float2(u00.x, -u00.y);
                VSplats& v = sV[l - 1];
                v.v00r = pk(u00.x, u10.x); v.v00i = pk(u00.y, u10.y); v.nv00i = pk(-u00.y, -u10.y);
                v.v01r = pk(u01.x, u11.x); v.v01i = pk(u01.y, u11.y); v.nv01i = pk(-u01.y, -u11.y);
                v.p0 = 0; v.p1 = 0;
            }
        }
    }
    for (int i = tid; i < 256; i += 128) {
        int j = i;
        #pragma unroll
        for (int w = 0; w < 8; w++) {
            int c = 7 - w, t = 7 - ((w + 3) & 7);
            if ((j >> c) & 1) j ^= (1 << t);
        }
        ((unsigned char*)sPv)[i] = (unsigned char)j;
    }
    __syncthreads();

    const unsigned lane = tid & 31;
    const unsigned s = lane & 15;
    const int b = blockIdx.x * 8 + (tid >> 5) * 2 + (lane >> 4);

    // ---- projection: 16 lanes per element, 8 float4 each ----
    float acc[8];
    #pragma unroll
    for (int w = 0; w < 8; w++) acc[w] = 0.f;
    const float4* xr = (const float4*)(x + (size_t)b * INDIM);
    #pragma unroll
    for (int c = 0; c < 8; c++) {
        float4 xv = xr[(c << 4) + s];
        #pragma unroll
        for (int w = 0; w < 8; w++) {
            float4 wv = ((const float4*)(sW[w]))[(c << 4) + s];
            acc[w] += xv.x * wv.x + xv.y * wv.y + xv.z * wv.z + xv.w * wv.w;
        }
    }
    {
        ull pa[4];
        #pragma unroll
        for (int t = 0; t < 4; t++) pa[t] = pk(acc[2 * t], acc[2 * t + 1]);
        #pragma unroll
        for (int off = 8; off > 0; off >>= 1) {
            #pragma unroll
            for (int t = 0; t < 4; t++) pa[t] = f2add(pa[t], shx64(pa[t], off));
        }
        #pragma unroll
        for (int t = 0; t < 4; t++) { float2 f = upk(pa[t]); acc[2 * t] = f.x; acc[2 * t + 1] = f.y; }
    }

    // ---- angles + fold layer-0 Rot ----
    float2 wa[8], wb[8];
    #pragma unroll
    for (int w = 0; w < 8; w++) {
        float t = (acc[w] + sPar[w]) * sPar[8 + w] + sPar[16 + w];
        float sg = 1.f / (1.f + __expf(-t));
        float cc, ss;
        __sincosf(sg * (0.5f * PI_F), &ss, &cc);
        float2 g00 = sG0[w][0], g01 = sG0[w][1];
        float2 g10 = sG0[w][2], g11 = sG0[w][3];
        wa[w] = make_float2(fmaf(g00.x, cc, g01.x * ss), fmaf(g00.y, cc, g01.y * ss));
        wb[w] = make_float2(fmaf(g10.x, cc, g11.x * ss), fmaf(g10.y, cc, g11.y * ss));
    }

    // ---- build product state ----
    float2 A = (s & 8) ? wb[0] : wa[0];
    A = cmul(A, (s & 4) ? wb[1] : wa[1]);
    A = cmul(A, (s & 2) ? wb[2] : wa[2]);
    A = cmul(A, (s & 1) ? wb[3] : wa[3]);

    float2 t4a = cmul(A, wa[4]), t4b = cmul(A, wb[4]);
    float2 t5[4];
    t5[0] = cmul(t4a, wa[5]); t5[1] = cmul(t4a, wb[5]);
    t5[2] = cmul(t4b, wa[5]); t5[3] = cmul(t4b, wb[5]);

    ull W7r  = pk(wa[7].x, wb[7].x);
    ull W7i  = pk(wa[7].y, wb[7].y);
    ull nW7i = pk(-wa[7].y, -wb[7].y);

    ull R[8], I[8];
    #pragma unroll
    for (int j = 0; j < 8; j++) {
        float2 C = cmul(t5[j >> 1], (j & 1) ? wb[6] : wa[6]);
        ull Cre = spl(C.x), Cim = spl(C.y);
        R[j] = f2fma(Cre, W7r, f2mul(Cim, nW7i));
        I[j] = f2fma(Cre, W7i, f2mul(Cim, W7r));
    }

    // ---- CNOT ring r=1: (7,6)(6,5)(5,4)(4,3)(3,2)(2,1)(1,0)(0,7) [amp-bit pairs] ----
    cnot_ll<3, 4>(R, I, lane);          // lane3 -> lane2
    cnot_ll<2, 2>(R, I, lane);          // lane2 -> lane1
    cnot_ll<1, 1>(R, I, lane);          // lane1 -> lane0
    cnot_lp<0, 4>(R, I, lane);          // lane0 -> pack4
    SWAPJ(4, 6); SWAPJ(5, 7);           // pack4 -> pack2
    SWAPJ(2, 3); SWAPJ(6, 7);           // pack2 -> pack1
    cnot_ph<1>(R, I);                   // pack1 -> half
    cnot_hl<8>(R, I);                   // half  -> lane3

    // ---- layer-1 Rots (wire 0..7) ----
    gate_shfl<3>(R, I, lane, &sSp[0][0]);
    gate_shfl<2>(R, I, lane, &sSp[0][1]);
    gate_shfl<1>(R, I, lane, &sSp[0][2]);
    gate_shfl<0>(R, I, lane, &sSp[0][3]);
    gate_cross<4>(R, I, &sSp[0][4]);
    gate_cross<2>(R, I, &sSp[0][5]);
    gate_cross<1>(R, I, &sSp[0][6]);
    gate_v(R, I, &sV[0]);

    // ---- CNOT ring r=2: (7,5)(6,4)(5,3)(4,2)(3,1)(2,0)(1,7)(0,6) ----
    cnot_ll<3, 2>(R, I, lane);          // lane3 -> lane1
    cnot_ll<2, 1>(R, I, lane);          // lane2 -> lane0
    cnot_lp<1, 4>(R, I, lane);          // lane1 -> pack4
    cnot_lp<0, 2>(R, I, lane);          // lane0 -> pack2
    SWAPJ(4, 5); SWAPJ(6, 7);           // pack4 -> pack1
    cnot_ph<2>(R, I);                   // pack2 -> half
    cnot_pl<1, 8>(R, I);                // pack1 -> lane3
    cnot_hl<4>(R, I);                   // half  -> lane2

    // ---- layer-2 Rots ----
    gate_shfl<3>(R, I, lane, &sSp[1][0]);
    gate_shfl<2>(R, I, lane, &sSp[1][1]);
    gate_shfl<1>(R, I, lane, &sSp[1][2]);
    gate_shfl<0>(R, I, lane, &sSp[1][3]);
    gate_cross<4>(R, I, &sSp[1][4]);
    gate_cross<2>(R, I, &sSp[1][5]);
    gate_cross<1>(R, I, &sSp[1][6]);
    gate_v(R, I, &sV[1]);

    // ---- measurement: sP(i^1)=sP(i)^0x21 -> halves share signs except wires 2,7 ----
    uint4 q0 = sPv[s];
    unsigned su[4] = {q0.x, q0.y, q0.z, q0.w};

    float zs[8];
    #pragma unroll
    for (int w = 0; w < 8; w++) zs[w] = 0.f;
    #pragma unroll
    for (int j = 0; j < 8; j++) {
        ull P = f2fma(R[j], R[j], f2mul(I[j], I[j]));
        float2 pp = upk(P);
        float sum = pp.x + pp.y;
        float dif = pp.x - pp.y;
        // even-amp byte offset = j*2 -> uint j>>1, shift (j&1)*16
        unsigned s8 = (su[j >> 1] >> ((j & 1) * 16)) & 0xffu;
        #pragma unroll
        for (int w = 0; w < 8; w++) {
            float val = (w == 2 || w == 7) ? dif : sum;
            unsigned sm = (s8 << (24 + w)) & 0x80000000u;
            zs[w] += __int_as_float(__float_as_int(val) ^ sm);
        }
    }

    ull zp[4];
    #pragma unroll
    for (int t = 0; t < 4; t++) zp[t] = pk(zs[2 * t], zs[2 * t + 1]);
    #pragma unroll
    for (int off = 8; off > 0; off >>= 1) {
        #pragma unroll
        for (int t = 0; t < 4; t++) zp[t] = f2add(zp[t], shx64(zp[t], off));
    }
    float2 z01 = upk(zp[0]), z23 = upk(zp[1]), z45 = upk(zp[2]), z67 = upk(zp[3]);
    float v = z01.x;
    if (s == 1) v = z01.y;
    if (s == 2) v = z23.x;
    if (s == 3) v = z23.y;
    if (s == 4) v = z45.x;
    if (s == 5) v = z45.y;
    if (s == 6) v = z67.x;
    if (s == 7) v = z67.y;
    if (s < 8) out[(size_t)b * 8 + s] = v;
}

extern "C" void kernel_launch(void* const* d_in, const int* in_sizes, int n_in,
                              void* d_out, int out_size) {
    const float* x     = (const float*)d_in[0];
    const float* W     = (const float*)d_in[1];
    const float* bvec  = (const float*)d_in[2];
    const float* scale = (const float*)d_in[3];
    const float* bias  = (const float*)d_in[4];
    const float* qw    = (const float*)d_in[5];
    float* out = (float*)d_out;
    qlayer_kernel<<<BATCHN / 8, 128>>>(x, W, bvec, scale, bias, qw, out);
}